// round 4
// baseline (speedup 1.0000x reference)
#include <cuda_runtime.h>
#include <cstdint>
#include <cstddef>

// Harness PTX target is base sm_103 — no tcgen05. Tensor path: mma.sync tf32 (HMMA).
// Pre-pass RNA-rounds inputs AND permutes k within each 8-float group so that
// the tf32 fragment pair (k, k+4) is adjacent in smem -> LDS.64 fragment loads.

// ---------------- problem constants ----------------
#define N_TOK   16384
#define F_DIM   1024
#define B_DIM   512
#define TILE_M  128
#define TILE_F  64
#define GCOLS   256          // 4 gates * TILE_F
#define KC      32           // K per chunk (128B rows)
#define NCHUNK  48
#define THREADS 512
#define STAGES  3

// ---------------- smem layout ----------------
#define ABYTES      (TILE_M * KC * 4)          // 16384
#define BBYTES      (GCOLS * KC * 4)           // 32768
#define STAGE_BYTES (ABYTES + BBYTES)          // 49152
#define GSM_PITCH   68
#define GSM_BYTES   (4 * 128 * GSM_PITCH * 4)  // 139264 (epilogue, unions stages)
#define SM_BIAS     (STAGES * STAGE_BYTES)     // 147456
#define SMEM_TOTAL  (SM_BIAS + 256 * 4)        // 148480

static_assert(GSM_BYTES <= STAGES * STAGE_BYTES, "epilogue union");
static_assert(SMEM_TOTAL <= 227 * 1024, "smem cap");

// ---------------- tf32-rounded, k-permuted scratch ----------------
__device__ float g_h [N_TOK * F_DIM];     // 64 MB
__device__ float g_x [N_TOK * B_DIM];     // 32 MB
__device__ float g_wh[4 * F_DIM * F_DIM]; // 16 MB
__device__ float g_wx[4 * F_DIM * B_DIM]; //  8 MB

// ---------------- helpers ----------------
static __device__ __forceinline__ uint32_t smem_u32(const void* p) {
    uint32_t a;
    asm("{ .reg .u64 t; cvta.to.shared.u64 t, %1; cvt.u32.u64 %0, t; }" : "=r"(a) : "l"(p));
    return a;
}

static __device__ __forceinline__ void cp16(uint32_t dst, const void* src) {
    asm volatile("cp.async.cg.shared.global [%0], [%1], 16;" :: "r"(dst), "l"(src) : "memory");
}

static __device__ __forceinline__ float rna_tf32(float f) {
    uint32_t r;
    asm("cvt.rna.tf32.f32 %0, %1;" : "=r"(r) : "f"(f));
    return __uint_as_float(r);
}

static __device__ __forceinline__ void lds64(uint32_t& a, uint32_t& b, uint32_t addr) {
    asm volatile("ld.shared.v2.b32 {%0,%1}, [%2];" : "=r"(a), "=r"(b) : "r"(addr));
}

static __device__ __forceinline__ void mma_tf32(float* c, const uint32_t* a, const uint32_t* b) {
    asm volatile(
        "mma.sync.aligned.m16n8k8.row.col.f32.tf32.tf32.f32 "
        "{%0,%1,%2,%3}, {%4,%5,%6,%7}, {%8,%9}, {%0,%1,%2,%3};"
        : "+f"(c[0]), "+f"(c[1]), "+f"(c[2]), "+f"(c[3])
        : "r"(a[0]), "r"(a[1]), "r"(a[2]), "r"(a[3]), "r"(b[0]), "r"(b[1]));
}

static __device__ __forceinline__ float sigf(float x) { return 1.0f / (1.0f + __expf(-x)); }
static __device__ __forceinline__ float tanh_fast(float x) {
    return 2.0f / (1.0f + __expf(-2.0f * x)) - 1.0f;
}

// ---- pre-pass: RNA-round + permute each 8-float k-group so pairs (k,k+4) are adjacent.
// slot layout per 8: {0,4,1,5, 2,6,3,7} -> thread lk reads slots (2lk,2lk+1) = k (lk, lk+4)
__global__ void __launch_bounds__(256) preperm_kernel(const float* __restrict__ src,
                                                      float4* __restrict__ dst, int n4) {
    int i = blockIdx.x * 256 + threadIdx.x;
    if (i < n4) {
        const float* s = src + (size_t)(i >> 1) * 8;
        float4 v;
        if (i & 1) { v.x = s[2]; v.y = s[6]; v.z = s[3]; v.w = s[7]; }
        else       { v.x = s[0]; v.y = s[4]; v.z = s[1]; v.w = s[5]; }
        v.x = rna_tf32(v.x); v.y = rna_tf32(v.y);
        v.z = rna_tf32(v.z); v.w = rna_tf32(v.w);
        dst[i] = v;
    }
}

// ---------------- mainloop chunk loader (512 threads) ----------------
static __device__ __forceinline__ void issue_chunk(int chunk, int slot, uint32_t sb, int tid,
                                                   int m_base, int c_base) {
    const float *asrc, *wk;
    int ld;
    if (chunk < 32) {
        asrc = g_h + (size_t)m_base * F_DIM + chunk * KC;
        wk   = g_wh + chunk * KC;
        ld   = F_DIM;
    } else {
        asrc = g_x + (size_t)m_base * B_DIM + (chunk - 32) * KC;
        wk   = g_wx + (chunk - 32) * KC;
        ld   = B_DIM;
    }

    const uint32_t abase = sb + (uint32_t)slot * STAGE_BYTES;
#pragma unroll
    for (int i = 0; i < 2; ++i) {     // A: 1024 float4 units
        int idx = tid + i * THREADS;
        int row = idx >> 3, u = idx & 7;
        cp16(abase + row * 128 + (uint32_t)((u ^ (row & 7)) << 4),
             asrc + (size_t)row * ld + u * 4);
    }
    const uint32_t bbase = abase + ABYTES;
#pragma unroll
    for (int i = 0; i < 4; ++i) {     // B: 2048 float4 units
        int idx = tid + i * THREADS;
        int rr = idx >> 3, u = idx & 7;
        int g = rr >> 6, r = rr & 63;
        cp16(bbase + rr * 128 + (uint32_t)((u ^ (rr & 7)) << 4),
             wk + (size_t)(g * F_DIM + c_base + r) * ld + u * 4);
    }
    asm volatile("cp.async.commit_group;" ::: "memory");
}

__global__ void __launch_bounds__(THREADS, 1)
lstm_mma_kernel(float* __restrict__ out,
                const float* __restrict__ c_prev,
                const float* __restrict__ bias) {
    extern __shared__ char smem[];
    const uint32_t sb = smem_u32(smem);
    const int tid = threadIdx.x;
    const int lane = tid & 31;
    const int wid = tid >> 5;          // 16 warps
    const int warp_m = wid & 1;        // token half (64 rows)
    const int warp_n = wid >> 1;       // 0..7: 32 gemm-cols each
    const int la = lane >> 2;          // 0..7
    const int lk = lane & 3;           // 0..3

    const int f_tile = blockIdx.x & 15;
    const int m_tile = blockIdx.x >> 4;
    const int m_base = m_tile * TILE_M;
    const int c_base = f_tile * TILE_F;

    float* bias_s = reinterpret_cast<float*>(smem + SM_BIAS);
    if (tid < 256) bias_s[tid] = bias[(tid >> 6) * F_DIM + c_base + (tid & 63)];

    float acc[4][4][4];
#pragma unroll
    for (int mt = 0; mt < 4; ++mt)
#pragma unroll
        for (int nt = 0; nt < 4; ++nt)
#pragma unroll
            for (int j = 0; j < 4; ++j) acc[mt][nt][j] = 0.0f;

    // prologue: fill 2 stages
    issue_chunk(0, 0, sb, tid, m_base, c_base);
    issue_chunk(1, 1, sb, tid, m_base, c_base);

    int slot = 0, wslot = 2;
    for (int ch = 0; ch < NCHUNK; ++ch) {
        if (ch < NCHUNK - 1) {
            asm volatile("cp.async.wait_group 1;" ::: "memory");
        } else {
            asm volatile("cp.async.wait_group 0;" ::: "memory");
        }
        __syncthreads();   // chunk ch visible to all; stage wslot fully consumed

        if (ch + 2 < NCHUNK) {
            issue_chunk(ch + 2, wslot, sb, tid, m_base, c_base);
            if (++wslot == STAGES) wslot = 0;
        }

        const uint32_t abase = sb + (uint32_t)slot * STAGE_BYTES;
        const uint32_t bbase = abase + ABYTES;
        if (++slot == STAGES) slot = 0;

#pragma unroll
        for (int ks = 0; ks < 4; ++ks) {
            // 16B-unit index for this thread's k-pair: u = ks*2 + (lk>>1), byte (lk&1)*8
            const uint32_t uo = (uint32_t)(ks * 2 + (lk >> 1));
            const uint32_t bo = (uint32_t)((lk & 1) << 3);

            uint32_t af[4][4];
#pragma unroll
            for (int mt = 0; mt < 4; ++mt) {
                const int r1 = warp_m * 64 + mt * 16 + la;
                const int r2 = r1 + 8;
                lds64(af[mt][0], af[mt][2],
                      abase + (uint32_t)r1 * 128 + (((uo ^ (uint32_t)(r1 & 7)) << 4) | bo));
                lds64(af[mt][1], af[mt][3],
                      abase + (uint32_t)r2 * 128 + (((uo ^ (uint32_t)(r2 & 7)) << 4) | bo));
            }
            uint32_t bf[4][2];
#pragma unroll
            for (int nt = 0; nt < 4; ++nt) {
                const int rn = warp_n * 32 + nt * 8 + la;
                lds64(bf[nt][0], bf[nt][1],
                      bbase + (uint32_t)rn * 128 + (((uo ^ (uint32_t)(rn & 7)) << 4) | bo));
            }
#pragma unroll
            for (int mt = 0; mt < 4; ++mt)
#pragma unroll
                for (int nt = 0; nt < 4; ++nt)
                    mma_tf32(acc[mt][nt], af[mt], bf[nt]);
        }
    }
    __syncthreads();   // stage buffers -> epilogue union

    // ---- epilogue: dump gate tiles to smem ----
    // gemm-col = warp_n*32 + nt*8 + 2lk(+1); gate = col>>6; f = col&63
    float* gsm = reinterpret_cast<float*>(smem);
    const int gate = warp_n >> 1;
    const int fbase = (warp_n & 1) * 32;
#pragma unroll
    for (int mt = 0; mt < 4; ++mt) {
#pragma unroll
        for (int nt = 0; nt < 4; ++nt) {
            const int r0 = warp_m * 64 + mt * 16 + la;
            const int f0 = fbase + nt * 8 + 2 * lk;
            const size_t o = ((size_t)(gate * 128 + r0)) * GSM_PITCH + f0;
            gsm[o]     = acc[mt][nt][0];
            gsm[o + 1] = acc[mt][nt][1];
            gsm[o + 8 * GSM_PITCH]     = acc[mt][nt][2];
            gsm[o + 8 * GSM_PITCH + 1] = acc[mt][nt][3];
        }
    }
    __syncthreads();

    // ---- gate math + coalesced global I/O ----
    const float* cpg = c_prev + (size_t)m_base * F_DIM + c_base;
    float* og = out + (size_t)m_base * F_DIM + c_base;
#pragma unroll
    for (int i = 0; i < (TILE_M * TILE_F) / THREADS; ++i) {
        const int idx = tid + i * THREADS;
        const int row = idx >> 6;
        const int f = idx & 63;
        const float xi = gsm[((size_t)(0 * 128 + row)) * GSM_PITCH + f] + bias_s[f];
        const float xf = gsm[((size_t)(1 * 128 + row)) * GSM_PITCH + f] + bias_s[64 + f];
        const float xg = gsm[((size_t)(2 * 128 + row)) * GSM_PITCH + f] + bias_s[128 + f];
        const float xo = gsm[((size_t)(3 * 128 + row)) * GSM_PITCH + f] + bias_s[192 + f];
        const float cv = sigf(xf) * cpg[(size_t)row * F_DIM + f] + sigf(xi) * tanh_fast(xg);
        og[(size_t)row * F_DIM + f] = sigf(xo) * tanh_fast(cv);
    }
}

extern "C" void kernel_launch(void* const* d_in, const int* in_sizes, int n_in,
                              void* d_out, int out_size) {
    const float* behavior = (const float*)d_in[0];
    const float* h_prev   = (const float*)d_in[1];
    const float* c_prev   = (const float*)d_in[2];
    const float* Wh       = (const float*)d_in[3];
    const float* Wx       = (const float*)d_in[4];
    const float* bias     = (const float*)d_in[5];

    float *p_h, *p_x, *p_wh, *p_wx;
    cudaGetSymbolAddress((void**)&p_h,  g_h);
    cudaGetSymbolAddress((void**)&p_x,  g_x);
    cudaGetSymbolAddress((void**)&p_wh, g_wh);
    cudaGetSymbolAddress((void**)&p_wx, g_wx);

    auto pr = [&](const float* s, float* d, int n) {
        int n4 = n / 4;
        preperm_kernel<<<(n4 + 255) / 256, 256>>>(s, (float4*)d, n4);
    };
    pr(h_prev,   p_h,  N_TOK * F_DIM);
    pr(behavior, p_x,  N_TOK * B_DIM);
    pr(Wh,       p_wh, 4 * F_DIM * F_DIM);
    pr(Wx,       p_wx, 4 * F_DIM * B_DIM);

    cudaFuncSetAttribute(lstm_mma_kernel,
                         cudaFuncAttributeMaxDynamicSharedMemorySize, SMEM_TOTAL);

    const int grid = (N_TOK / TILE_M) * (F_DIM / TILE_F);  // 2048
    lstm_mma_kernel<<<grid, THREADS, SMEM_TOTAL>>>((float*)d_out, c_prev, bias);
}

// round 5
// speedup vs baseline: 1.8290x; 1.8290x over previous
#include <cuda_runtime.h>
#include <cuda_fp16.h>
#include <cstdint>
#include <cstddef>

// Harness PTX target is base sm_103 — no tcgen05. Tensor path: mma.sync f16 (HMMA).
// fp16 has the SAME 10-bit mantissa as tf32, but m16n8k16 does 2x K per instruction.
// Operands (|x|<~6) are far inside fp16 range -> precision identical to tf32 path.

// ---------------- problem constants ----------------
#define N_TOK   16384
#define F_DIM   1024
#define B_DIM   512
#define TILE_M  128
#define TILE_F  64
#define GCOLS   256          // 4 gates * TILE_F
#define KC      64           // K elements per chunk (128B fp16 rows)
#define NCHUNK  24           // 1536 / 64
#define THREADS 256
#define STAGES  3

// ---------------- smem layout ----------------
#define ABYTES      (TILE_M * KC * 2)          // 16384
#define BBYTES      (GCOLS * KC * 2)           // 32768
#define STAGE_BYTES (ABYTES + BBYTES)          // 49152
#define GSM_PITCH   68
#define GSM_BYTES   (4 * 128 * GSM_PITCH * 4)  // 139264 (epilogue, unions stages)
#define SM_BIAS     (STAGES * STAGE_BYTES)     // 147456
#define SMEM_TOTAL  (SM_BIAS + 256 * 4)        // 148480

static_assert(GSM_BYTES <= STAGES * STAGE_BYTES, "epilogue union");
static_assert(SMEM_TOTAL <= 227 * 1024, "smem cap");

// ---------------- fp16 scratch (device globals are the allowed scratch) ------------
__device__ __half g_h [N_TOK * F_DIM];     // 32 MB
__device__ __half g_x [N_TOK * B_DIM];     // 16 MB
__device__ __half g_wh[4 * F_DIM * F_DIM]; //  8 MB
__device__ __half g_wx[4 * F_DIM * B_DIM]; //  4 MB

// ---------------- helpers ----------------
static __device__ __forceinline__ uint32_t smem_u32(const void* p) {
    uint32_t a;
    asm("{ .reg .u64 t; cvta.to.shared.u64 t, %1; cvt.u32.u64 %0, t; }" : "=r"(a) : "l"(p));
    return a;
}

static __device__ __forceinline__ void cp16(uint32_t dst, const void* src) {
    asm volatile("cp.async.cg.shared.global [%0], [%1], 16;" :: "r"(dst), "l"(src) : "memory");
}

static __device__ __forceinline__ uint32_t lds32(uint32_t addr) {
    uint32_t v;
    asm volatile("ld.shared.b32 %0, [%1];" : "=r"(v) : "r"(addr));
    return v;
}

static __device__ __forceinline__ void mma_f16(float* c, const uint32_t* a, const uint32_t* b) {
    asm volatile(
        "mma.sync.aligned.m16n8k16.row.col.f32.f16.f16.f32 "
        "{%0,%1,%2,%3}, {%4,%5,%6,%7}, {%8,%9}, {%0,%1,%2,%3};"
        : "+f"(c[0]), "+f"(c[1]), "+f"(c[2]), "+f"(c[3])
        : "r"(a[0]), "r"(a[1]), "r"(a[2]), "r"(a[3]), "r"(b[0]), "r"(b[1]));
}

static __device__ __forceinline__ float sigf(float x) { return 1.0f / (1.0f + __expf(-x)); }
static __device__ __forceinline__ float tanh_fast(float x) {
    return 2.0f / (1.0f + __expf(-2.0f * x)) - 1.0f;
}

// ---------------- pre-pass: fp32 -> fp16 (rn) ----------------
__global__ void __launch_bounds__(256) preconv_kernel(const float4* __restrict__ src,
                                                      uint4* __restrict__ dst, int n8) {
    int i = blockIdx.x * 256 + threadIdx.x;
    if (i < n8) {
        float4 a = src[2 * i], b = src[2 * i + 1];
        uint4 o;
        o.x = __half2_raw(__floats2half2_rn(a.x, a.y)).x |
              ((uint32_t)0);  // pack below
        __half2 p0 = __floats2half2_rn(a.x, a.y);
        __half2 p1 = __floats2half2_rn(a.z, a.w);
        __half2 p2 = __floats2half2_rn(b.x, b.y);
        __half2 p3 = __floats2half2_rn(b.z, b.w);
        o.x = *reinterpret_cast<uint32_t*>(&p0);
        o.y = *reinterpret_cast<uint32_t*>(&p1);
        o.z = *reinterpret_cast<uint32_t*>(&p2);
        o.w = *reinterpret_cast<uint32_t*>(&p3);
        dst[i] = o;
    }
}

// ---------------- mainloop chunk loader ----------------
static __device__ __forceinline__ void issue_chunk(int chunk, int slot, uint32_t sb, int tid,
                                                   int m_base, int c_base) {
    const __half *asrc, *wk;
    int ld;
    if (chunk < 16) {                 // K in [0,1024): h_prev @ Wh^T
        asrc = g_h + (size_t)m_base * F_DIM + chunk * KC;
        wk   = g_wh + chunk * KC;
        ld   = F_DIM;
    } else {                          // K in [1024,1536): behavior @ Wx^T
        asrc = g_x + (size_t)m_base * B_DIM + (chunk - 16) * KC;
        wk   = g_wx + (chunk - 16) * KC;
        ld   = B_DIM;
    }

    const uint32_t abase = sb + (uint32_t)slot * STAGE_BYTES;
#pragma unroll
    for (int i = 0; i < 4; ++i) {     // A: 128 rows x 128B = 1024 16B-units
        int idx = tid + i * THREADS;
        int row = idx >> 3, u = idx & 7;
        cp16(abase + row * 128 + (uint32_t)((u ^ (row & 7)) << 4),
             asrc + (size_t)row * ld + u * 8);
    }
    const uint32_t bbase = abase + ABYTES;
#pragma unroll
    for (int i = 0; i < 8; ++i) {     // B: 256 rows x 128B = 2048 16B-units
        int idx = tid + i * THREADS;
        int rr = idx >> 3, u = idx & 7;
        int g = rr >> 6, r = rr & 63;
        cp16(bbase + rr * 128 + (uint32_t)((u ^ (rr & 7)) << 4),
             wk + (size_t)(g * F_DIM + c_base + r) * ld + u * 8);
    }
    asm volatile("cp.async.commit_group;" ::: "memory");
}

__global__ void __launch_bounds__(THREADS, 1)
lstm_mma_kernel(float* __restrict__ out,
                const float* __restrict__ c_prev,
                const float* __restrict__ bias) {
    extern __shared__ char smem[];
    const uint32_t sb = smem_u32(smem);
    const int tid = threadIdx.x;
    const int lane = tid & 31;
    const int wid = tid >> 5;
    const int warp_m = wid & 1;        // token half (64 rows)
    const int warp_n = wid >> 1;       // gate (0..3), 64 gemm-cols each
    const int la = lane >> 2;          // 0..7
    const int lk = lane & 3;           // 0..3

    const int f_tile = blockIdx.x & 15;
    const int m_tile = blockIdx.x >> 4;
    const int m_base = m_tile * TILE_M;
    const int c_base = f_tile * TILE_F;

    float* bias_s = reinterpret_cast<float*>(smem + SM_BIAS);
    bias_s[tid] = bias[(tid >> 6) * F_DIM + c_base + (tid & 63)];

    float acc[4][8][4];
#pragma unroll
    for (int mt = 0; mt < 4; ++mt)
#pragma unroll
        for (int nt = 0; nt < 8; ++nt)
#pragma unroll
            for (int j = 0; j < 4; ++j) acc[mt][nt][j] = 0.0f;

    // prologue: fill 2 stages
    issue_chunk(0, 0, sb, tid, m_base, c_base);
    issue_chunk(1, 1, sb, tid, m_base, c_base);

    int slot = 0, wslot = 2;
    for (int ch = 0; ch < NCHUNK; ++ch) {
        if (ch < NCHUNK - 1) {
            asm volatile("cp.async.wait_group 1;" ::: "memory");
        } else {
            asm volatile("cp.async.wait_group 0;" ::: "memory");
        }
        __syncthreads();   // chunk ch visible; stage wslot free (consumed last iter)

        if (ch + 2 < NCHUNK) {
            issue_chunk(ch + 2, wslot, sb, tid, m_base, c_base);
            if (++wslot == STAGES) wslot = 0;
        }

        const uint32_t abase = sb + (uint32_t)slot * STAGE_BYTES;
        const uint32_t bbase = abase + ABYTES;
        if (++slot == STAGES) slot = 0;

        // fp16 fragment addressing: k-pair (2lk,2lk+1) at byte 4lk within unit 2ks;
        // k+8 pair at unit 2ks+1. SW128: unit ^= (row & 7).
#pragma unroll
        for (int ks = 0; ks < 4; ++ks) {          // 4 x K=16 per chunk (KC=64)
            const uint32_t u0 = (uint32_t)(2 * ks);
            const uint32_t bo = (uint32_t)(lk << 2);

            uint32_t af[4][4];
#pragma unroll
            for (int mt = 0; mt < 4; ++mt) {
                const int r1 = warp_m * 64 + mt * 16 + la;
                const int r2 = r1 + 8;
                const uint32_t s1 = (uint32_t)(r1 & 7), s2 = (uint32_t)(r2 & 7);
                af[mt][0] = lds32(abase + (uint32_t)r1 * 128 + (((u0 + 0) ^ s1) << 4) + bo);
                af[mt][1] = lds32(abase + (uint32_t)r2 * 128 + (((u0 + 0) ^ s2) << 4) + bo);
                af[mt][2] = lds32(abase + (uint32_t)r1 * 128 + (((u0 + 1) ^ s1) << 4) + bo);
                af[mt][3] = lds32(abase + (uint32_t)r2 * 128 + (((u0 + 1) ^ s2) << 4) + bo);
            }
            uint32_t bf[8][2];
#pragma unroll
            for (int nt = 0; nt < 8; ++nt) {
                const int rn = warp_n * 64 + nt * 8 + la;
                const uint32_t sn = (uint32_t)(rn & 7);
                bf[nt][0] = lds32(bbase + (uint32_t)rn * 128 + (((u0 + 0) ^ sn) << 4) + bo);
                bf[nt][1] = lds32(bbase + (uint32_t)rn * 128 + (((u0 + 1) ^ sn) << 4) + bo);
            }
#pragma unroll
            for (int mt = 0; mt < 4; ++mt)
#pragma unroll
                for (int nt = 0; nt < 8; ++nt)
                    mma_f16(acc[mt][nt], af[mt], bf[nt]);
        }
    }
    __syncthreads();   // stage buffers -> epilogue union

    // ---- epilogue: dump 4 gate tiles (128 x 64 each) to smem ----
    float* gsm = reinterpret_cast<float*>(smem);
#pragma unroll
    for (int mt = 0; mt < 4; ++mt) {
#pragma unroll
        for (int nt = 0; nt < 8; ++nt) {
            const int r0 = warp_m * 64 + mt * 16 + la;
            const int f0 = nt * 8 + 2 * lk;
            const size_t o = ((size_t)(warp_n * 128 + r0)) * GSM_PITCH + f0;
            gsm[o]     = acc[mt][nt][0];
            gsm[o + 1] = acc[mt][nt][1];
            gsm[o + 8 * GSM_PITCH]     = acc[mt][nt][2];
            gsm[o + 8 * GSM_PITCH + 1] = acc[mt][nt][3];
        }
    }
    __syncthreads();

    // ---- gate math + coalesced global I/O ----
    const float* cpg = c_prev + (size_t)m_base * F_DIM + c_base;
    float* og = out + (size_t)m_base * F_DIM + c_base;
#pragma unroll
    for (int i = 0; i < (TILE_M * TILE_F) / THREADS; ++i) {
        const int idx = tid + i * THREADS;
        const int row = idx >> 6;
        const int f = idx & 63;
        const float xi = gsm[((size_t)(0 * 128 + row)) * GSM_PITCH + f] + bias_s[f];
        const float xf = gsm[((size_t)(1 * 128 + row)) * GSM_PITCH + f] + bias_s[64 + f];
        const float xg = gsm[((size_t)(2 * 128 + row)) * GSM_PITCH + f] + bias_s[128 + f];
        const float xo = gsm[((size_t)(3 * 128 + row)) * GSM_PITCH + f] + bias_s[192 + f];
        const float cv = sigf(xf) * cpg[(size_t)row * F_DIM + f] + sigf(xi) * tanh_fast(xg);
        og[(size_t)row * F_DIM + f] = sigf(xo) * tanh_fast(cv);
    }
}

extern "C" void kernel_launch(void* const* d_in, const int* in_sizes, int n_in,
                              void* d_out, int out_size) {
    const float* behavior = (const float*)d_in[0];
    const float* h_prev   = (const float*)d_in[1];
    const float* c_prev   = (const float*)d_in[2];
    const float* Wh       = (const float*)d_in[3];
    const float* Wx       = (const float*)d_in[4];
    const float* bias     = (const float*)d_in[5];

    __half *p_h, *p_x, *p_wh, *p_wx;
    cudaGetSymbolAddress((void**)&p_h,  g_h);
    cudaGetSymbolAddress((void**)&p_x,  g_x);
    cudaGetSymbolAddress((void**)&p_wh, g_wh);
    cudaGetSymbolAddress((void**)&p_wx, g_wx);

    auto pr = [&](const float* s, __half* d, int n) {
        int n8 = n / 8;
        preconv_kernel<<<(n8 + 255) / 256, 256>>>((const float4*)s, (uint4*)d, n8);
    };
    pr(h_prev,   p_h,  N_TOK * F_DIM);
    pr(behavior, p_x,  N_TOK * B_DIM);
    pr(Wh,       p_wh, 4 * F_DIM * F_DIM);
    pr(Wx,       p_wx, 4 * F_DIM * B_DIM);

    cudaFuncSetAttribute(lstm_mma_kernel,
                         cudaFuncAttributeMaxDynamicSharedMemorySize, SMEM_TOTAL);

    const int grid = (N_TOK / TILE_M) * (F_DIM / TILE_F);  // 2048
    lstm_mma_kernel<<<grid, THREADS, SMEM_TOTAL>>>((float*)d_out, c_prev, bias);
}

// round 6
// speedup vs baseline: 1.8685x; 1.0216x over previous
#include <cuda_runtime.h>
#include <cuda_fp16.h>
#include <cstdint>
#include <cstddef>

// Harness PTX target is base sm_103 — no tcgen05. Tensor path: mma.sync f16 m16n8k16
// (HMMA) with fp32 accum. Fragments fetched via ldmatrix.x4 (4x fewer shared ops
// than scalar LDS). fp16 mantissa == tf32 mantissa; operands are small -> safe.

// ---------------- problem constants ----------------
#define N_TOK   16384
#define F_DIM   1024
#define B_DIM   512
#define TILE_M  128
#define TILE_F  64
#define GCOLS   256          // 4 gates * TILE_F
#define KC      64           // K elements per chunk (128B fp16 rows)
#define NCHUNK  24           // 1536 / 64
#define THREADS 256
#define STAGES  3

// ---------------- smem layout ----------------
#define ABYTES      (TILE_M * KC * 2)          // 16384
#define BBYTES      (GCOLS * KC * 2)           // 32768
#define STAGE_BYTES (ABYTES + BBYTES)          // 49152
#define GSM_PITCH   68
#define GSM_BYTES   (4 * 128 * GSM_PITCH * 4)  // 139264 (epilogue, unions stages)
#define SM_BIAS     (STAGES * STAGE_BYTES)     // 147456
#define SMEM_TOTAL  (SM_BIAS + 256 * 4)        // 148480

static_assert(GSM_BYTES <= STAGES * STAGE_BYTES, "epilogue union");
static_assert(SMEM_TOTAL <= 227 * 1024, "smem cap");

// ---------------- fp16 scratch ----------------
__device__ __half g_h [N_TOK * F_DIM];     // 32 MB
__device__ __half g_x [N_TOK * B_DIM];     // 16 MB
__device__ __half g_wh[4 * F_DIM * F_DIM]; //  8 MB
__device__ __half g_wx[4 * F_DIM * B_DIM]; //  4 MB

// ---------------- helpers ----------------
static __device__ __forceinline__ uint32_t smem_u32(const void* p) {
    uint32_t a;
    asm("{ .reg .u64 t; cvta.to.shared.u64 t, %1; cvt.u32.u64 %0, t; }" : "=r"(a) : "l"(p));
    return a;
}

static __device__ __forceinline__ void cp16(uint32_t dst, const void* src) {
    asm volatile("cp.async.cg.shared.global [%0], [%1], 16;" :: "r"(dst), "l"(src) : "memory");
}

static __device__ __forceinline__ void ldsm4(uint32_t* r, uint32_t addr) {
    asm volatile("ldmatrix.sync.aligned.m8n8.x4.shared.b16 {%0,%1,%2,%3}, [%4];"
                 : "=r"(r[0]), "=r"(r[1]), "=r"(r[2]), "=r"(r[3]) : "r"(addr));
}

static __device__ __forceinline__ void mma_f16(float* c, const uint32_t* a, const uint32_t* b) {
    asm volatile(
        "mma.sync.aligned.m16n8k16.row.col.f32.f16.f16.f32 "
        "{%0,%1,%2,%3}, {%4,%5,%6,%7}, {%8,%9}, {%0,%1,%2,%3};"
        : "+f"(c[0]), "+f"(c[1]), "+f"(c[2]), "+f"(c[3])
        : "r"(a[0]), "r"(a[1]), "r"(a[2]), "r"(a[3]), "r"(b[0]), "r"(b[1]));
}

static __device__ __forceinline__ float sigf(float x) { return 1.0f / (1.0f + __expf(-x)); }
static __device__ __forceinline__ float tanh_fast(float x) {
    return 2.0f / (1.0f + __expf(-2.0f * x)) - 1.0f;
}

// ---------------- pre-pass: fp32 -> fp16 (rn) ----------------
__global__ void __launch_bounds__(256) preconv_kernel(const float4* __restrict__ src,
                                                      uint4* __restrict__ dst, int n8) {
    int i = blockIdx.x * 256 + threadIdx.x;
    if (i < n8) {
        float4 a = src[2 * i], b = src[2 * i + 1];
        __half2 p0 = __floats2half2_rn(a.x, a.y);
        __half2 p1 = __floats2half2_rn(a.z, a.w);
        __half2 p2 = __floats2half2_rn(b.x, b.y);
        __half2 p3 = __floats2half2_rn(b.z, b.w);
        uint4 o;
        o.x = *reinterpret_cast<uint32_t*>(&p0);
        o.y = *reinterpret_cast<uint32_t*>(&p1);
        o.z = *reinterpret_cast<uint32_t*>(&p2);
        o.w = *reinterpret_cast<uint32_t*>(&p3);
        dst[i] = o;
    }
}

// ---------------- mainloop chunk loader ----------------
static __device__ __forceinline__ void issue_chunk(int chunk, int slot, uint32_t sb, int tid,
                                                   int m_base, int c_base) {
    const __half *asrc, *wk;
    int ld;
    if (chunk < 16) {                 // K in [0,1024): h_prev @ Wh^T
        asrc = g_h + (size_t)m_base * F_DIM + chunk * KC;
        wk   = g_wh + chunk * KC;
        ld   = F_DIM;
    } else {                          // K in [1024,1536): behavior @ Wx^T
        asrc = g_x + (size_t)m_base * B_DIM + (chunk - 16) * KC;
        wk   = g_wx + (chunk - 16) * KC;
        ld   = B_DIM;
    }

    const uint32_t abase = sb + (uint32_t)slot * STAGE_BYTES;
#pragma unroll
    for (int i = 0; i < 4; ++i) {     // A: 128 rows x 128B, SW128
        int idx = tid + i * THREADS;
        int row = idx >> 3, u = idx & 7;
        cp16(abase + row * 128 + (uint32_t)((u ^ (row & 7)) << 4),
             asrc + (size_t)row * ld + u * 8);
    }
    const uint32_t bbase = abase + ABYTES;
#pragma unroll
    for (int i = 0; i < 8; ++i) {     // B: 256 rows x 128B, SW128
        int idx = tid + i * THREADS;
        int rr = idx >> 3, u = idx & 7;
        int g = rr >> 6, r = rr & 63;
        cp16(bbase + rr * 128 + (uint32_t)((u ^ (rr & 7)) << 4),
             wk + (size_t)(g * F_DIM + c_base + r) * ld + u * 8);
    }
    asm volatile("cp.async.commit_group;" ::: "memory");
}

__global__ void __launch_bounds__(THREADS, 1)
lstm_mma_kernel(float* __restrict__ out,
                const float* __restrict__ c_prev,
                const float* __restrict__ bias) {
    extern __shared__ char smem[];
    const uint32_t sb = smem_u32(smem);
    const int tid = threadIdx.x;
    const int lane = tid & 31;
    const int wid = tid >> 5;
    const int warp_m = wid & 1;        // token half (64 rows)
    const int warp_n = wid >> 1;       // gate (0..3), 64 gemm-cols each
    const int la = lane >> 2;          // 0..7
    const int lk = lane & 3;           // 0..3

    const int f_tile = blockIdx.x & 15;
    const int m_tile = blockIdx.x >> 4;
    const int m_base = m_tile * TILE_M;
    const int c_base = f_tile * TILE_F;

    float* bias_s = reinterpret_cast<float*>(smem + SM_BIAS);
    bias_s[tid] = bias[(tid >> 6) * F_DIM + c_base + (tid & 63)];

    // ---- per-lane ldmatrix address components ----
    const int q    = lane >> 3;        // quad / matrix index
    const int lrow = lane & 7;         // row within 8-row group; == (row&7) everywhere
    // A quads: matrix q -> (row + 8*(q&1), k-half q>>1)
    const uint32_t aStat = (uint32_t)(warp_m * 64 + (q & 1) * 8 + lrow) * 128u;
    const int kqA = q >> 1;
    // B quads: matrix q -> (n-tile + 8*(q>>1), k-half q&1)
    const uint32_t bStat = (uint32_t)(warp_n * 64 + (q >> 1) * 8 + lrow) * 128u;
    const int kqB = q & 1;

    float acc[4][8][4];
#pragma unroll
    for (int mt = 0; mt < 4; ++mt)
#pragma unroll
        for (int nt = 0; nt < 8; ++nt)
#pragma unroll
            for (int j = 0; j < 4; ++j) acc[mt][nt][j] = 0.0f;

    issue_chunk(0, 0, sb, tid, m_base, c_base);
    issue_chunk(1, 1, sb, tid, m_base, c_base);

    int slot = 0, wslot = 2;
    for (int ch = 0; ch < NCHUNK; ++ch) {
        if (ch < NCHUNK - 1) {
            asm volatile("cp.async.wait_group 1;" ::: "memory");
        } else {
            asm volatile("cp.async.wait_group 0;" ::: "memory");
        }
        __syncthreads();

        if (ch + 2 < NCHUNK) {
            issue_chunk(ch + 2, wslot, sb, tid, m_base, c_base);
            if (++wslot == STAGES) wslot = 0;
        }

        const uint32_t abase = sb + (uint32_t)slot * STAGE_BYTES;
        const uint32_t bbase = abase + ABYTES;
        if (++slot == STAGES) slot = 0;

#pragma unroll
        for (int ks = 0; ks < 4; ++ks) {          // 4 x K=16 per chunk
            const uint32_t uA = (uint32_t)(((2 * ks + kqA) ^ lrow) << 4);
            const uint32_t uB = (uint32_t)(((2 * ks + kqB) ^ lrow) << 4);

            uint32_t af[4][4];
#pragma unroll
            for (int mt = 0; mt < 4; ++mt)
                ldsm4(af[mt], abase + aStat + (uint32_t)(mt * 16 * 128) + uA);

            uint32_t bq[4][4];                    // each x4 covers 2 n-tiles
#pragma unroll
            for (int np = 0; np < 4; ++np)
                ldsm4(bq[np], bbase + bStat + (uint32_t)(np * 16 * 128) + uB);

#pragma unroll
            for (int mt = 0; mt < 4; ++mt)
#pragma unroll
                for (int nt = 0; nt < 8; ++nt)
                    mma_f16(acc[mt][nt], af[mt], &bq[nt >> 1][(nt & 1) * 2]);
        }
    }
    __syncthreads();   // stage buffers -> epilogue union

    // ---- epilogue: dump 4 gate tiles (128 x 64 each) to smem ----
    float* gsm = reinterpret_cast<float*>(smem);
#pragma unroll
    for (int mt = 0; mt < 4; ++mt) {
#pragma unroll
        for (int nt = 0; nt < 8; ++nt) {
            const int r0 = warp_m * 64 + mt * 16 + la;
            const int f0 = nt * 8 + 2 * lk;
            const size_t o = ((size_t)(warp_n * 128 + r0)) * GSM_PITCH + f0;
            gsm[o]     = acc[mt][nt][0];
            gsm[o + 1] = acc[mt][nt][1];
            gsm[o + 8 * GSM_PITCH]     = acc[mt][nt][2];
            gsm[o + 8 * GSM_PITCH + 1] = acc[mt][nt][3];
        }
    }
    __syncthreads();

    // ---- gate math + coalesced global I/O ----
    const float* cpg = c_prev + (size_t)m_base * F_DIM + c_base;
    float* og = out + (size_t)m_base * F_DIM + c_base;
#pragma unroll
    for (int i = 0; i < (TILE_M * TILE_F) / THREADS; ++i) {
        const int idx = tid + i * THREADS;
        const int row = idx >> 6;
        const int f = idx & 63;
        const float xi = gsm[((size_t)(0 * 128 + row)) * GSM_PITCH + f] + bias_s[f];
        const float xf = gsm[((size_t)(1 * 128 + row)) * GSM_PITCH + f] + bias_s[64 + f];
        const float xg = gsm[((size_t)(2 * 128 + row)) * GSM_PITCH + f] + bias_s[128 + f];
        const float xo = gsm[((size_t)(3 * 128 + row)) * GSM_PITCH + f] + bias_s[192 + f];
        const float cv = sigf(xf) * cpg[(size_t)row * F_DIM + f] + sigf(xi) * tanh_fast(xg);
        og[(size_t)row * F_DIM + f] = sigf(xo) * tanh_fast(cv);
    }
}

extern "C" void kernel_launch(void* const* d_in, const int* in_sizes, int n_in,
                              void* d_out, int out_size) {
    const float* behavior = (const float*)d_in[0];
    const float* h_prev   = (const float*)d_in[1];
    const float* c_prev   = (const float*)d_in[2];
    const float* Wh       = (const float*)d_in[3];
    const float* Wx       = (const float*)d_in[4];
    const float* bias     = (const float*)d_in[5];

    __half *p_h, *p_x, *p_wh, *p_wx;
    cudaGetSymbolAddress((void**)&p_h,  g_h);
    cudaGetSymbolAddress((void**)&p_x,  g_x);
    cudaGetSymbolAddress((void**)&p_wh, g_wh);
    cudaGetSymbolAddress((void**)&p_wx, g_wx);

    auto pr = [&](const float* s, __half* d, int n) {
        int n8 = n / 8;
        preconv_kernel<<<(n8 + 255) / 256, 256>>>((const float4*)s, (uint4*)d, n8);
    };
    pr(h_prev,   p_h,  N_TOK * F_DIM);
    pr(behavior, p_x,  N_TOK * B_DIM);
    pr(Wh,       p_wh, 4 * F_DIM * F_DIM);
    pr(Wx,       p_wx, 4 * F_DIM * B_DIM);

    cudaFuncSetAttribute(lstm_mma_kernel,
                         cudaFuncAttributeMaxDynamicSharedMemorySize, SMEM_TOTAL);

    const int grid = (N_TOK / TILE_M) * (F_DIM / TILE_F);  // 2048
    lstm_mma_kernel<<<grid, THREADS, SMEM_TOTAL>>>((float*)d_out, c_prev, bias);
}

// round 7
// speedup vs baseline: 2.6079x; 1.3957x over previous
#include <cuda_runtime.h>
#include <cuda_fp16.h>
#include <cstdint>
#include <cstddef>

// Harness PTX target is base sm_103 — no tcgen05. Tensor path: mma.sync f16 m16n8k16
// (fallback HMMA, fixed MAC/cyc). This round: 2 CTAs/SM so barrier phases interleave
// and the tensor unit stays fed. Warp tile 64x32, CTA tile 128x(4x32 gates).

// ---------------- problem constants ----------------
#define N_TOK   16384
#define F_DIM   1024
#define B_DIM   512
#define TILE_M  128
#define TILE_F  32
#define GCOLS   128          // 4 gates * TILE_F
#define KC      64           // K elements per chunk (128B fp16 rows)
#define NCHUNK  24           // 1536 / 64
#define THREADS 256
#define STAGES  3

// ---------------- smem layout ----------------
#define ABYTES      (TILE_M * KC * 2)          // 16384
#define BBYTES      (GCOLS * KC * 2)           // 16384
#define STAGE_BYTES (ABYTES + BBYTES)          // 32768
#define GSM_PITCH   36
#define GSM_BYTES   (4 * 128 * GSM_PITCH * 4)  // 73728 (epilogue, unions stages)
#define SM_BIAS     (STAGES * STAGE_BYTES)     // 98304
#define SMEM_TOTAL  (SM_BIAS + 128 * 4)        // 98816  (x2 CTAs = 197632 <= 227KB)

static_assert(GSM_BYTES <= STAGES * STAGE_BYTES, "epilogue union");
static_assert(2 * SMEM_TOTAL <= 227 * 1024, "2 CTAs/SM smem");

// ---------------- fp16 scratch ----------------
__device__ __half g_h [N_TOK * F_DIM];     // 32 MB
__device__ __half g_x [N_TOK * B_DIM];     // 16 MB
__device__ __half g_wh[4 * F_DIM * F_DIM]; //  8 MB
__device__ __half g_wx[4 * F_DIM * B_DIM]; //  4 MB

// ---------------- helpers ----------------
static __device__ __forceinline__ uint32_t smem_u32(const void* p) {
    uint32_t a;
    asm("{ .reg .u64 t; cvta.to.shared.u64 t, %1; cvt.u32.u64 %0, t; }" : "=r"(a) : "l"(p));
    return a;
}

static __device__ __forceinline__ void cp16(uint32_t dst, const void* src) {
    asm volatile("cp.async.cg.shared.global [%0], [%1], 16;" :: "r"(dst), "l"(src) : "memory");
}

static __device__ __forceinline__ void ldsm4(uint32_t* r, uint32_t addr) {
    asm volatile("ldmatrix.sync.aligned.m8n8.x4.shared.b16 {%0,%1,%2,%3}, [%4];"
                 : "=r"(r[0]), "=r"(r[1]), "=r"(r[2]), "=r"(r[3]) : "r"(addr));
}

static __device__ __forceinline__ void mma_f16(float* c, const uint32_t* a, const uint32_t* b) {
    asm volatile(
        "mma.sync.aligned.m16n8k16.row.col.f32.f16.f16.f32 "
        "{%0,%1,%2,%3}, {%4,%5,%6,%7}, {%8,%9}, {%0,%1,%2,%3};"
        : "+f"(c[0]), "+f"(c[1]), "+f"(c[2]), "+f"(c[3])
        : "r"(a[0]), "r"(a[1]), "r"(a[2]), "r"(a[3]), "r"(b[0]), "r"(b[1]));
}

static __device__ __forceinline__ float sigf(float x) { return 1.0f / (1.0f + __expf(-x)); }
static __device__ __forceinline__ float tanh_fast(float x) {
    return 2.0f / (1.0f + __expf(-2.0f * x)) - 1.0f;
}

// ---------------- pre-pass: fp32 -> fp16 (rn) ----------------
__global__ void __launch_bounds__(256) preconv_kernel(const float4* __restrict__ src,
                                                      uint4* __restrict__ dst, int n8) {
    int i = blockIdx.x * 256 + threadIdx.x;
    if (i < n8) {
        float4 a = src[2 * i], b = src[2 * i + 1];
        __half2 p0 = __floats2half2_rn(a.x, a.y);
        __half2 p1 = __floats2half2_rn(a.z, a.w);
        __half2 p2 = __floats2half2_rn(b.x, b.y);
        __half2 p3 = __floats2half2_rn(b.z, b.w);
        uint4 o;
        o.x = *reinterpret_cast<uint32_t*>(&p0);
        o.y = *reinterpret_cast<uint32_t*>(&p1);
        o.z = *reinterpret_cast<uint32_t*>(&p2);
        o.w = *reinterpret_cast<uint32_t*>(&p3);
        dst[i] = o;
    }
}

// ---------------- mainloop chunk loader ----------------
static __device__ __forceinline__ void issue_chunk(int chunk, int slot, uint32_t sb, int tid,
                                                   int m_base, int c_base) {
    const __half *asrc, *wk;
    int ld;
    if (chunk < 16) {                 // K in [0,1024): h_prev @ Wh^T
        asrc = g_h + (size_t)m_base * F_DIM + chunk * KC;
        wk   = g_wh + chunk * KC;
        ld   = F_DIM;
    } else {                          // K in [1024,1536): behavior @ Wx^T
        asrc = g_x + (size_t)m_base * B_DIM + (chunk - 16) * KC;
        wk   = g_wx + (chunk - 16) * KC;
        ld   = B_DIM;
    }

    const uint32_t abase = sb + (uint32_t)slot * STAGE_BYTES;
#pragma unroll
    for (int i = 0; i < 4; ++i) {     // A: 128 rows x 128B, SW128
        int idx = tid + i * THREADS;
        int row = idx >> 3, u = idx & 7;
        cp16(abase + row * 128 + (uint32_t)((u ^ (row & 7)) << 4),
             asrc + (size_t)row * ld + u * 8);
    }
    const uint32_t bbase = abase + ABYTES;
#pragma unroll
    for (int i = 0; i < 4; ++i) {     // B: 128 rows x 128B, SW128
        int idx = tid + i * THREADS;
        int rr = idx >> 3, u = idx & 7;
        int g = rr >> 5, r = rr & 31;
        cp16(bbase + rr * 128 + (uint32_t)((u ^ (rr & 7)) << 4),
             wk + (size_t)(g * F_DIM + c_base + r) * ld + u * 8);
    }
    asm volatile("cp.async.commit_group;" ::: "memory");
}

__global__ void __launch_bounds__(THREADS, 2)
lstm_mma_kernel(float* __restrict__ out,
                const float* __restrict__ c_prev,
                const float* __restrict__ bias) {
    extern __shared__ char smem[];
    const uint32_t sb = smem_u32(smem);
    const int tid = threadIdx.x;
    const int lane = tid & 31;
    const int wid = tid >> 5;
    const int warp_m = wid & 1;        // token half (64 rows)
    const int warp_n = wid >> 1;       // gate (0..3), 32 gemm-cols each
    const int la = lane >> 2;          // 0..7
    const int lk = lane & 3;           // 0..3

    const int f_tile = blockIdx.x & 31;
    const int m_tile = blockIdx.x >> 5;
    const int m_base = m_tile * TILE_M;
    const int c_base = f_tile * TILE_F;

    float* bias_s = reinterpret_cast<float*>(smem + SM_BIAS);
    if (tid < 128) bias_s[tid] = bias[(tid >> 5) * F_DIM + c_base + (tid & 31)];

    // ---- per-lane ldmatrix address components ----
    const int q    = lane >> 3;        // quad / matrix index
    const int lrow = lane & 7;
    const uint32_t aStat = (uint32_t)(warp_m * 64 + (q & 1) * 8 + lrow) * 128u;
    const int kqA = q >> 1;
    const uint32_t bStat = (uint32_t)(warp_n * 32 + (q >> 1) * 8 + lrow) * 128u;
    const int kqB = q & 1;

    float acc[4][4][4];
#pragma unroll
    for (int mt = 0; mt < 4; ++mt)
#pragma unroll
        for (int nt = 0; nt < 4; ++nt)
#pragma unroll
            for (int j = 0; j < 4; ++j) acc[mt][nt][j] = 0.0f;

    issue_chunk(0, 0, sb, tid, m_base, c_base);
    issue_chunk(1, 1, sb, tid, m_base, c_base);

    int slot = 0, wslot = 2;
    for (int ch = 0; ch < NCHUNK; ++ch) {
        if (ch < NCHUNK - 1) {
            asm volatile("cp.async.wait_group 1;" ::: "memory");
        } else {
            asm volatile("cp.async.wait_group 0;" ::: "memory");
        }
        __syncthreads();

        if (ch + 2 < NCHUNK) {
            issue_chunk(ch + 2, wslot, sb, tid, m_base, c_base);
            if (++wslot == STAGES) wslot = 0;
        }

        const uint32_t abase = sb + (uint32_t)slot * STAGE_BYTES;
        const uint32_t bbase = abase + ABYTES;
        if (++slot == STAGES) slot = 0;

#pragma unroll
        for (int ks = 0; ks < 4; ++ks) {          // 4 x K=16 per chunk
            const uint32_t uA = (uint32_t)(((2 * ks + kqA) ^ lrow) << 4);
            const uint32_t uB = (uint32_t)(((2 * ks + kqB) ^ lrow) << 4);

            uint32_t af[4][4];
#pragma unroll
            for (int mt = 0; mt < 4; ++mt)
                ldsm4(af[mt], abase + aStat + (uint32_t)(mt * 16 * 128) + uA);

            uint32_t bq[2][4];                    // each x4 covers 2 n-tiles
#pragma unroll
            for (int np = 0; np < 2; ++np)
                ldsm4(bq[np], bbase + bStat + (uint32_t)(np * 16 * 128) + uB);

#pragma unroll
            for (int mt = 0; mt < 4; ++mt)
#pragma unroll
                for (int nt = 0; nt < 4; ++nt)
                    mma_f16(acc[mt][nt], af[mt], &bq[nt >> 1][(nt & 1) * 2]);
        }
    }
    __syncthreads();   // stage buffers -> epilogue union

    // ---- epilogue: dump 4 gate tiles (128 x 32 each) to smem ----
    float* gsm = reinterpret_cast<float*>(smem);
#pragma unroll
    for (int mt = 0; mt < 4; ++mt) {
#pragma unroll
        for (int nt = 0; nt < 4; ++nt) {
            const int r0 = warp_m * 64 + mt * 16 + la;
            const int f0 = nt * 8 + 2 * lk;
            const size_t o = ((size_t)(warp_n * 128 + r0)) * GSM_PITCH + f0;
            gsm[o]     = acc[mt][nt][0];
            gsm[o + 1] = acc[mt][nt][1];
            gsm[o + 8 * GSM_PITCH]     = acc[mt][nt][2];
            gsm[o + 8 * GSM_PITCH + 1] = acc[mt][nt][3];
        }
    }
    __syncthreads();

    // ---- gate math + coalesced global I/O ----
    const float* cpg = c_prev + (size_t)m_base * F_DIM + c_base;
    float* og = out + (size_t)m_base * F_DIM + c_base;
#pragma unroll
    for (int i = 0; i < (TILE_M * TILE_F) / THREADS; ++i) {
        const int idx = tid + i * THREADS;
        const int row = idx >> 5;
        const int f = idx & 31;
        const float xi = gsm[((size_t)(0 * 128 + row)) * GSM_PITCH + f] + bias_s[f];
        const float xf = gsm[((size_t)(1 * 128 + row)) * GSM_PITCH + f] + bias_s[32 + f];
        const float xg = gsm[((size_t)(2 * 128 + row)) * GSM_PITCH + f] + bias_s[64 + f];
        const float xo = gsm[((size_t)(3 * 128 + row)) * GSM_PITCH + f] + bias_s[96 + f];
        const float cv = sigf(xf) * cpg[(size_t)row * F_DIM + f] + sigf(xi) * tanh_fast(xg);
        og[(size_t)row * F_DIM + f] = sigf(xo) * tanh_fast(cv);
    }
}

extern "C" void kernel_launch(void* const* d_in, const int* in_sizes, int n_in,
                              void* d_out, int out_size) {
    const float* behavior = (const float*)d_in[0];
    const float* h_prev   = (const float*)d_in[1];
    const float* c_prev   = (const float*)d_in[2];
    const float* Wh       = (const float*)d_in[3];
    const float* Wx       = (const float*)d_in[4];
    const float* bias     = (const float*)d_in[5];

    __half *p_h, *p_x, *p_wh, *p_wx;
    cudaGetSymbolAddress((void**)&p_h,  g_h);
    cudaGetSymbolAddress((void**)&p_x,  g_x);
    cudaGetSymbolAddress((void**)&p_wh, g_wh);
    cudaGetSymbolAddress((void**)&p_wx, g_wx);

    auto pr = [&](const float* s, __half* d, int n) {
        int n8 = n / 8;
        preconv_kernel<<<(n8 + 255) / 256, 256>>>((const float4*)s, (uint4*)d, n8);
    };
    pr(h_prev,   p_h,  N_TOK * F_DIM);
    pr(behavior, p_x,  N_TOK * B_DIM);
    pr(Wh,       p_wh, 4 * F_DIM * F_DIM);
    pr(Wx,       p_wx, 4 * F_DIM * B_DIM);

    cudaFuncSetAttribute(lstm_mma_kernel,
                         cudaFuncAttributeMaxDynamicSharedMemorySize, SMEM_TOTAL);

    const int grid = (N_TOK / TILE_M) * (F_DIM / TILE_F);  // 128 * 32 = 4096
    lstm_mma_kernel<<<grid, THREADS, SMEM_TOTAL>>>((float*)d_out, c_prev, bias);
}